// round 8
// baseline (speedup 1.0000x reference)
#include <cuda_runtime.h>
#include <cuda_bf16.h>

// JPEG q=99 luma-only path (chroma provably constant for grayscale-replicated input).
// Warp per channel; 8 lanes per 8x8 tile; transforms in registers, transposes via shfl.

#define C1f 0.98078528040323044913f
#define C2f 0.92387953251128675613f
#define C3f 0.83146961230254523708f
#define C4f 0.70710678118654752440f
#define C5f 0.55557023301960222474f
#define C6f 0.38268343236508977173f
#define C7f 0.19509032201612826785f

__constant__ float YQc[64] = {
    16.f, 11.f, 10.f, 16.f, 24.f, 40.f, 51.f, 61.f,
    12.f, 12.f, 14.f, 19.f, 26.f, 58.f, 60.f, 55.f,
    14.f, 13.f, 16.f, 24.f, 40.f, 57.f, 69.f, 56.f,
    14.f, 17.f, 22.f, 29.f, 51.f, 87.f, 80.f, 62.f,
    18.f, 22.f, 37.f, 56.f, 68.f,109.f,103.f, 77.f,
    24.f, 35.f, 55.f, 64.f, 81.f,104.f,113.f, 92.f,
    49.f, 64.f, 78.f, 87.f,103.f,121.f,120.f,101.f,
    72.f, 92.f, 95.f, 98.f,112.f,100.f,103.f, 99.f
};

__device__ __forceinline__ void dct8(const float in[8], float out[8]) {
    float s0 = in[0] + in[7], s1 = in[1] + in[6], s2 = in[2] + in[5], s3 = in[3] + in[4];
    float d0 = in[0] - in[7], d1 = in[1] - in[6], d2 = in[2] - in[5], d3 = in[3] - in[4];
    out[0] = (s0 + s3) + (s1 + s2);
    out[4] = C4f * ((s0 + s3) - (s1 + s2));
    out[2] = C2f*s0 + C6f*s1 - C6f*s2 - C2f*s3;
    out[6] = C6f*s0 - C2f*s1 + C2f*s2 - C6f*s3;
    out[1] = C1f*d0 + C3f*d1 + C5f*d2 + C7f*d3;
    out[3] = C3f*d0 - C7f*d1 - C1f*d2 - C5f*d3;
    out[5] = C5f*d0 - C1f*d1 + C7f*d2 + C3f*d3;
    out[7] = C7f*d0 - C5f*d1 + C3f*d2 - C1f*d3;
}

__device__ __forceinline__ void idct8(const float e[8], float out[8]) {
    float ev0 = e[0] + C2f*e[2] + C4f*e[4] + C6f*e[6];
    float ev1 = e[0] + C6f*e[2] - C4f*e[4] - C2f*e[6];
    float ev2 = e[0] - C6f*e[2] - C4f*e[4] + C2f*e[6];
    float ev3 = e[0] - C2f*e[2] + C4f*e[4] - C6f*e[6];
    float od0 = C1f*e[1] + C3f*e[3] + C5f*e[5] + C7f*e[7];
    float od1 = C3f*e[1] - C7f*e[3] - C1f*e[5] - C5f*e[7];
    float od2 = C5f*e[1] - C1f*e[3] + C7f*e[5] + C3f*e[7];
    float od3 = C7f*e[1] - C5f*e[3] + C3f*e[5] - C1f*e[7];
    out[0] = ev0 + od0;  out[7] = ev0 - od0;
    out[1] = ev1 + od1;  out[6] = ev1 - od1;
    out[2] = ev2 + od2;  out[5] = ev2 - od2;
    out[3] = ev3 + od3;  out[4] = ev3 - od3;
}

// 8x8 transpose within an 8-lane group: bitwise lane/reg index exchange.
__device__ __forceinline__ void transpose8(float a[8], int lane) {
    #pragma unroll
    for (int m = 1; m < 8; m <<= 1) {
        #pragma unroll
        for (int j0 = 0; j0 < 8; j0++) {
            if (j0 & m) continue;
            const int jA = j0 | m;
            bool hi = (lane & m) != 0;
            float send = hi ? a[j0] : a[jA];
            float recv = __shfl_xor_sync(0xffffffffu, send, m);
            if (hi) a[j0] = recv; else a[jA] = recv;
        }
    }
}

#define WARPS_BLK 8
#define STRIDE 197

__global__ __launch_bounds__(256, 5)
void jpeg_y_kernel(const float* __restrict__ x, float* __restrict__ out, int nch)
{
    __shared__ float shin [WARPS_BLK * STRIDE];
    __shared__ float shout[WARPS_BLK * STRIDE];
    __shared__ float shq[64], shiq[64];

    const int tid  = threadIdx.x;
    const int lane = tid & 31;
    const int wrp  = tid >> 5;
    const int tile = lane >> 3;       // 0..3
    const int l    = lane & 7;        // row within tile / freq v
    const int br   = tile >> 1, bc = tile & 1;
    const int gch  = blockIdx.x * WARPS_BLK + wrp;
    const bool act = (gch < nch);
    const int base = wrp * STRIDE;

    // quant tables (once per block)
    if (tid < 64) {
        float q = YQc[tid] * 0.02f;   // factor for quality 99
        shq[tid]  = q;
        shiq[tid] = 1.0f / q;
    }

    // ---- stage channel (coalesced, warp-local) + min/max on the fly ----
    float mn = 3.4e38f, mx = -3.4e38f;
    if (act) {
        const float* xp = x + (size_t)gch * 196;
        #pragma unroll
        for (int k = 0; k < 7; k++) {
            int i = lane + 32 * k;
            if (i < 196) {
                float v = xp[i];
                shin[base + i] = v;
                mn = fminf(mn, v); mx = fmaxf(mx, v);
            }
        }
    }
    __syncthreads();          // tables + own-warp staging visibility
    if (!act) return;

    #pragma unroll
    for (int o = 16; o; o >>= 1) {
        mn = fminf(mn, __shfl_xor_sync(0xffffffffu, mn, o));
        mx = fmaxf(mx, __shfl_xor_sync(0xffffffffu, mx, o));
    }
    const float rng = mx - mn + 1e-5f;
    const float sc  = 255.0f / rng;

    // ---- pass 1: row DCT (lane = tile row, regs = y) ----
    float a[8];
    {
        const int row = min(max(8 * br + l - 1, 0), 13);
        float w[8];
        #pragma unroll
        for (int y = 0; y < 8; y++) {
            int col = min(max(8 * bc + y - 1, 0), 13);
            w[y] = (shin[base + row * 14 + col] - mn) * sc - 128.0f;
        }
        dct8(w, a);               // a[v]
    }

    // ---- transpose: lane = v, regs = x ----
    transpose8(a, lane);

    // ---- pass 2: column DCT + diff_round quant/dequant ----
    {
        float d[8];
        dct8(a, d);               // d[u], lane = v
        const float alv = (l == 0) ? C4f : 1.0f;
        #pragma unroll
        for (int u = 0; u < 8; u++) {
            float aa = ((u == 0) ? C4f : 1.0f) * alv;
            float qs = shq [u * 8 + l];
            float iq = shiq[u * 8 + l];
            float D  = 0.25f * aa * d[u];
            float qd = D * iq;
            float rr = rintf(qd);            // round-half-even == jnp.round
            float dd = qd - rr;
            float q  = rr + dd * dd * dd;
            a[u] = (q * qs) * aa;            // dequant, IDCT alpha folded
        }
    }

    // ---- pass 3: IDCT over u (regs), lane = v ----
    {
        float t[8];
        idct8(a, t);
        #pragma unroll
        for (int i = 0; i < 8; i++) a[i] = t[i];   // a[x]
    }

    // ---- transpose: lane = x, regs = v ----
    transpose8(a, lane);

    // ---- pass 4: IDCT over v + crop/clip/denorm -> shared ----
    {
        float p[8];
        idct8(a, p);              // p[y], lane = tile row x
        const float dsc = rng * (1.0f / 255.0f);
        const int i = 8 * br + l - 1;
        if ((unsigned)i < 14u) {
            #pragma unroll
            for (int y = 0; y < 8; y++) {
                int j = 8 * bc + y - 1;
                if ((unsigned)j < 14u) {
                    float pv = 0.25f * p[y] + 128.0f;
                    pv = fminf(fmaxf(pv, 0.0f), 255.0f);
                    shout[base + i * 14 + j] = pv * dsc + mn;
                }
            }
        }
    }
    __syncwarp();

    // ---- de-stage output (coalesced, warp-local) ----
    {
        float* op = out + (size_t)gch * 196;
        #pragma unroll
        for (int k = 0; k < 7; k++) {
            int i = lane + 32 * k;
            if (i < 196) op[i] = shout[base + i];
        }
    }
}

extern "C" void kernel_launch(void* const* d_in, const int* in_sizes, int n_in,
                              void* d_out, int out_size)
{
    const float* x = (const float*)d_in[0];
    float* out = (float*)d_out;
    int nch = in_sizes[0] / 196;                      // 32*1024 channels of 14x14
    int blocks = (nch + WARPS_BLK - 1) / WARPS_BLK;   // 4096
    jpeg_y_kernel<<<blocks, 256>>>(x, out, nch);
}